// round 14
// baseline (speedup 1.0000x reference)
#include <cuda_runtime.h>
#include <cuda_fp16.h>
#include <cstdint>

// GINConv: out = (1+eps)*feat + segment_sum(feat[edge_src] -> edge_dst)
// N=100000 nodes, D=64 fp32, E=1200000 edges.
//
// Round-14: gather measured AT the LTS cap (12.4 TB/s) -> only bytes help.
// fp16 messages, fixed from R11's failed attempt:
//  - cvt merged INTO bin_kernel (each block converts a feat slice; no extra
//    launch; bin kernel is latency-bound with BW headroom).
//  - gather loads fp16 rows (128B) with 4 BATCHED independent uint2 loads
//    per unrolled step (R11 serialized load->add per row), fp32 accumulate,
//    exact fp32 self term. Bytes 363MB -> ~210MB.
// rel_err ~2e-4 (<< 1e-3). Pipeline stays 2 launches.

static constexpr int D4 = 16;             // 64 floats = 16 float4 per row
static constexpr int NPB = 136;           // nodes per bin -> 736 bins for N=100000
static constexpr int BIN_CAP = 1920;      // mean 1632 + ~7 sigma
static constexpr int NBINS_MAX = 1024;
static constexpr int SBUF = 4096;         // edges per bin_kernel block
static constexpr int BK_THREADS = 1024;
static constexpr int EPT = SBUF / BK_THREADS;   // 4 edges per thread
static constexpr int OVF_MAX = 65536;
static constexpr int N_MAX = 131072;

__device__ int g_bin_cnt[NBINS_MAX];                  // zero on entry (invariant)
__device__ int g_bin[(size_t)NBINS_MAX * BIN_CAP];    // packed (dl<<17)|src
__device__ int g_ovf_cnt;                             // zero on entry (invariant)
__device__ int g_done;                                // zero on entry (invariant)
__device__ int2 g_ovf[OVF_MAX];                       // (dst, src) overflow edges
__device__ __align__(16) __half g_feat16[(size_t)N_MAX * 64];

// block-wide exclusive scan, 1024 threads
__device__ __forceinline__ int block_exscan_1024(int v) {
    int lane = threadIdx.x & 31;
    int warp = threadIdx.x >> 5;   // 0..31
    int x = v;
#pragma unroll
    for (int o = 1; o < 32; o <<= 1) {
        int y = __shfl_up_sync(0xFFFFFFFFu, x, o);
        if (lane >= o) x += y;
    }
    __shared__ int wsum32[32];
    if (lane == 31) wsum32[warp] = x;
    __syncthreads();
    if (warp == 0) {
        int w = wsum32[lane];
#pragma unroll
        for (int o = 1; o < 32; o <<= 1) {
            int y = __shfl_up_sync(0xFFFFFFFFu, w, o);
            if (lane >= o) w += y;
        }
        wsum32[lane] = w;
    }
    __syncthreads();
    int base = (warp > 0) ? wsum32[warp - 1] : 0;
    return base + x - v;
}

// block-wide exclusive scan, 256 threads
__device__ __forceinline__ int block_exscan_256(int v) {
    int lane = threadIdx.x & 31;
    int warp = threadIdx.x >> 5;   // 0..7
    int x = v;
#pragma unroll
    for (int o = 1; o < 32; o <<= 1) {
        int y = __shfl_up_sync(0xFFFFFFFFu, x, o);
        if (lane >= o) x += y;
    }
    __shared__ int wsum8[8];
    if (lane == 31) wsum8[warp] = x;
    __syncthreads();
    if (warp == 0) {
        int w = (lane < 8) ? wsum8[lane] : 0;
#pragma unroll
        for (int o = 1; o < 8; o <<= 1) {
            int y = __shfl_up_sync(0xFFFFFFFFu, w, o);
            if (lane >= o) w += y;
        }
        if (lane < 8) wsum8[lane] = w;
    }
    __syncthreads();
    int base = (warp > 0) ? wsum8[warp - 1] : 0;
    return base + x - v;
}

// ---------- kernel 1: bin edges + convert feat slice to fp16 ----------

__global__ void __launch_bounds__(BK_THREADS) bin_kernel(
    const int* __restrict__ edge_src,
    const int* __restrict__ edge_dst,
    const float4* __restrict__ feat,
    int n_edges, int nbins, int n4) {
    __shared__ int s_hist[NBINS_MAX];
    __shared__ int s_off[NBINS_MAX];
    __shared__ int s_gbase[NBINS_MAX];
    __shared__ int s_cur[NBINS_MAX];
    __shared__ int s_buf[SBUF];
    __shared__ unsigned short s_bin[SBUF];

    int tid = threadIdx.x;
    int e0 = blockIdx.x * SBUF;
    int e1 = min(e0 + SBUF, n_edges);
    int ecnt = e1 - e0;

    if (tid < NBINS_MAX) s_hist[tid] = 0;

    // merged cvt: this block converts its contiguous slice of feat -> fp16
    {
        int per = (n4 + gridDim.x - 1) / (int)gridDim.x;
        int c0 = blockIdx.x * per;
        int c1 = min(c0 + per, n4);
        for (int i = c0 + tid; i < c1; i += BK_THREADS) {
            float4 f = __ldg(feat + i);
            __half2 h0 = __floats2half2_rn(f.x, f.y);
            __half2 h1 = __floats2half2_rn(f.z, f.w);
            uint2 u;
            u.x = *reinterpret_cast<unsigned*>(&h0);
            u.y = *reinterpret_cast<unsigned*>(&h1);
            *reinterpret_cast<uint2*>(g_feat16 + (size_t)i * 4) = u;
        }
    }
    __syncthreads();

    // load 4 edges/thread into registers (int4 when possible)
    int base = e0 + tid * EPT;
    int dd[EPT], ss[EPT];
    int m = 0;
    if (base + EPT <= e1) {
        int4 d = __ldg((const int4*)(edge_dst + base));
        int4 s = __ldg((const int4*)(edge_src + base));
        dd[0] = d.x; dd[1] = d.y; dd[2] = d.z; dd[3] = d.w;
        ss[0] = s.x; ss[1] = s.y; ss[2] = s.z; ss[3] = s.w;
        m = EPT;
    } else {
        for (int i = base; i < e1; ++i) {
            dd[m] = __ldg(edge_dst + i);
            ss[m] = __ldg(edge_src + i);
            ++m;
        }
    }

    // pass A: histogram over bins (from registers)
#pragma unroll
    for (int k = 0; k < EPT; ++k)
        if (k < m) atomicAdd(&s_hist[dd[k] / NPB], 1);
    __syncthreads();

    // local scan (1 entry/thread over 1024)
    {
        int h0 = s_hist[tid];
        int ex = block_exscan_1024(h0);
        s_off[tid] = ex;
        s_cur[tid] = ex;
    }
    __syncthreads();

    // reserve global space per bin (exact counts)
    if (tid < nbins) {
        int h = s_hist[tid];
        s_gbase[tid] = h ? atomicAdd(&g_bin_cnt[tid], h) : 0;
    }
    __syncthreads();

    // pass B: scatter packed edges + bin ids into smem staging
#pragma unroll
    for (int k = 0; k < EPT; ++k) {
        if (k < m) {
            int bin = dd[k] / NPB;
            int dl = dd[k] - bin * NPB;
            int pos = atomicAdd(&s_cur[bin], 1);
            s_buf[pos] = (dl << 17) | ss[k];
            s_bin[pos] = (unsigned short)bin;
        }
    }
    __syncthreads();

    // flush: entry-parallel; adjacent entries (same bin) target adjacent
    // global slots -> mostly-coalesced stores
    for (int i = tid; i < ecnt; i += BK_THREADS) {
        int bin = s_bin[i];
        int v = s_buf[i];
        int gpos = s_gbase[bin] + (i - s_off[bin]);
        if (gpos < BIN_CAP) {
            g_bin[(size_t)bin * BIN_CAP + gpos] = v;
        } else {
            int o = atomicAdd(&g_ovf_cnt, 1);
            if (o < OVF_MAX)
                g_ovf[o] = make_int2(bin * NPB + (v >> 17), v & 0x1FFFF);
        }
    }
}

// ---------- kernel 2: per-bin counting sort + fp16 gather (batched loads) ----------

__device__ __forceinline__ uint2 ld_row16(int s, int lane) {
    return __ldg(reinterpret_cast<const uint2*>(g_feat16 + (size_t)s * 64) + lane);
}

__device__ __forceinline__ void acc_u2(float4& acc, uint2 u) {
    __half2 h0 = *reinterpret_cast<__half2*>(&u.x);
    __half2 h1 = *reinterpret_cast<__half2*>(&u.y);
    float2 f0 = __half22float2(h0);
    float2 f1 = __half22float2(h1);
    acc.x += f0.x; acc.y += f0.y; acc.z += f1.x; acc.w += f1.y;
}

__global__ void __launch_bounds__(256) bin_gather_kernel(
    const float4* __restrict__ feat,
    const float* __restrict__ eps,
    float4* __restrict__ out,
    int n_nodes) {
    __shared__ int s_hist[NPB + 2];
    __shared__ int s_off[NPB + 2];
    __shared__ int s_cur[NPB + 2];
    __shared__ int s_in[BIN_CAP];
    __shared__ int s_src[BIN_CAP];
    __shared__ int s_ovn;

    int tid = threadIdx.x;
    int b = blockIdx.x;
    int node0 = b * NPB;
    int nloc = min(NPB, n_nodes - node0);

    int cnt = g_bin_cnt[b];
    int used = cnt < BIN_CAP ? cnt : BIN_CAP;
    const int* bsrc = g_bin + (size_t)b * BIN_CAP;

    for (int j = tid; j < NPB + 2; j += 256) s_hist[j] = 0;
    if (tid == 0) {
        int n = g_ovf_cnt;
        s_ovn = n < OVF_MAX ? n : OVF_MAX;
    }

    // stage the bin into SMEM (coalesced, once)
    for (int i = tid; i < used; i += 256) s_in[i] = __ldg(bsrc + i);
    __syncthreads();

    // histogram over local nodes (from SMEM)
    for (int i = tid; i < used; i += 256)
        atomicAdd(&s_hist[s_in[i] >> 17], 1);
    __syncthreads();

    // scan (1 entry/thread covers 256 >= NPB+2)
    {
        int j0 = tid;
        int h0 = (j0 < NPB + 2) ? s_hist[j0] : 0;
        int ex = block_exscan_256(h0);
        if (j0 < NPB + 2) { s_off[j0] = ex; s_cur[j0] = ex; }
    }
    __syncthreads();

    // counting-scatter srcs grouped by local node (SMEM -> SMEM)
    for (int i = tid; i < used; i += 256) {
        int v = s_in[i];
        int pos = atomicAdd(&s_cur[v >> 17], 1);
        s_src[pos] = v & 0x1FFFF;
    }
    __syncthreads();

    // gather: 16 groups x 16 lanes; group g handles nodes g, g+16, ...
    int group = tid >> 4;
    int lane = tid & 15;
    float sc = 1.0f + __ldg(eps);
    int ovn = s_ovn;

    for (int nl = group; nl < nloc; nl += 16) {
        int node = node0 + nl;
        int beg = s_off[nl];
        int end = s_off[nl + 1];

        float4 acc = make_float4(0.f, 0.f, 0.f, 0.f);
        int e = beg;
        // 4 batched INDEPENDENT loads, then convert+add
        for (; e + 4 <= end; e += 4) {
            int s0 = s_src[e];
            int s1 = s_src[e + 1];
            int s2 = s_src[e + 2];
            int s3 = s_src[e + 3];
            uint2 u0 = ld_row16(s0, lane);
            uint2 u1 = ld_row16(s1, lane);
            uint2 u2 = ld_row16(s2, lane);
            uint2 u3 = ld_row16(s3, lane);
            acc_u2(acc, u0);
            acc_u2(acc, u1);
            acc_u2(acc, u2);
            acc_u2(acc, u3);
        }
        for (; e < end; ++e) {
            uint2 u = ld_row16(s_src[e], lane);
            acc_u2(acc, u);
        }

        // inline overflow application (expected ovn == 0), exact fp32
        for (int k = 0; k < ovn; ++k) {
            int2 oe = g_ovf[k];
            if (oe.x == node) {
                float4 v = __ldg(feat + (size_t)oe.y * D4 + lane);
                acc.x += v.x; acc.y += v.y; acc.z += v.z; acc.w += v.w;
            }
        }

        float4 f = __ldg(feat + (size_t)node * D4 + lane);
        float4 o;
        o.x = fmaf(sc, f.x, acc.x);
        o.y = fmaf(sc, f.y, acc.y);
        o.z = fmaf(sc, f.z, acc.z);
        o.w = fmaf(sc, f.w, acc.w);
        out[(size_t)node * D4 + lane] = o;
    }

    // restore invariants for next call
    __syncthreads();
    if (tid == 0) {
        g_bin_cnt[b] = 0;
        int t = atomicAdd(&g_done, 1);
        if (t == (int)gridDim.x - 1) {   // last block: all others already read g_ovf_cnt
            g_done = 0;
            g_ovf_cnt = 0;
        }
    }
}

// ---------- fallback (atomic) path for unexpected shapes ----------

__global__ void gin_init_kernel(const float4* __restrict__ feat,
                                const float* __restrict__ eps,
                                float4* __restrict__ out,
                                int n4) {
    int i = blockIdx.x * blockDim.x + threadIdx.x;
    if (i >= n4) return;
    float s = 1.0f + __ldg(eps);
    float4 f = __ldg(feat + i);
    f.x *= s; f.y *= s; f.z *= s; f.w *= s;
    out[i] = f;
}

__global__ void __launch_bounds__(256) gin_edge_atomic_kernel(
    const float4* __restrict__ feat,
    const int* __restrict__ edge_src,
    const int* __restrict__ edge_dst,
    float4* __restrict__ out,
    int n_edges) {
    int gid = blockIdx.x * blockDim.x + threadIdx.x;
    int eid = gid >> 4;
    int lane = gid & 15;
    if (eid >= n_edges) return;
    int s = __ldg(edge_src + eid);
    int d = __ldg(edge_dst + eid);
    float4 v = __ldg(feat + (size_t)s * D4 + lane);
    float4* dst = out + (size_t)d * D4 + lane;
    asm volatile(
        "red.global.add.v4.f32 [%0], {%1, %2, %3, %4};"
        :: "l"(dst), "f"(v.x), "f"(v.y), "f"(v.z), "f"(v.w)
        : "memory");
}

extern "C" void kernel_launch(void* const* d_in, const int* in_sizes, int n_in,
                              void* d_out, int out_size) {
    const float* feat     = (const float*)d_in[0];
    const float* eps      = (const float*)d_in[1];
    const int*   edge_src = (const int*)d_in[2];
    const int*   edge_dst = (const int*)d_in[3];
    float*       out      = (float*)d_out;

    int n_feat  = in_sizes[0];          // N * 64
    int n_edges = in_sizes[2];          // E
    int n_nodes = n_feat / 64;

    int nbins = (n_nodes + NPB - 1) / NPB;

    // src must fit in 17 bits; bins + fp16 staging within static scratch
    if (n_nodes > N_MAX || nbins > NBINS_MAX) {
        int n4 = n_feat / 4;
        gin_init_kernel<<<(n4 + 255) / 256, 256>>>(
            (const float4*)feat, eps, (float4*)out, n4);
        long long total = (long long)n_edges * 16;
        gin_edge_atomic_kernel<<<(int)((total + 255) / 256), 256>>>(
            (const float4*)feat, edge_src, edge_dst, (float4*)out, n_edges);
        return;
    }

    int n4 = n_feat / 4;

    // 1. bin edges + fp16 staging (g_bin_cnt zero by invariant)
    int nblk = (n_edges + SBUF - 1) / SBUF;
    bin_kernel<<<nblk, BK_THREADS>>>(edge_src, edge_dst,
                                     (const float4*)feat, n_edges, nbins, n4);

    // 2. per-bin SMEM sort + fp16 gather + residual; applies overflow inline;
    //    re-zeroes g_bin_cnt, g_ovf_cnt, g_done
    bin_gather_kernel<<<nbins, 256>>>(
        (const float4*)feat, eps, (float4*)out, n_nodes);
}

// round 15
// speedup vs baseline: 1.1055x; 1.1055x over previous
#include <cuda_runtime.h>
#include <cstdint>

// GINConv: out = (1+eps)*feat + segment_sum(feat[edge_src] -> edge_dst)
// N=100000 nodes, D=64 fp32, E=1200000 edges.
//
// Round-15: fp16 permanently reverted (two implementations both slower =>
// gather is NOT byte-bound; it is latency/occupancy-bound: ncu L2=47.7%,
// occ=58.9% with grid-limited 5 blocks/SM). This is R13 (best, 37.0us) with
// ONE change: NPB 136->100 => 1000 gather blocks, all resident in a single
// wave at ~6.76 blocks/SM = 84% occupancy (vs 62.5%), no straggler wave.
// BIN_CAP 1472 (mean 1200 + ~7.9 sigma). Everything else identical.

static constexpr int D4 = 16;             // 64 floats = 16 float4 per row
static constexpr int NPB = 100;           // nodes per bin -> 1000 bins for N=100000
static constexpr int BIN_CAP = 1472;      // mean 1200 + ~7.9 sigma
static constexpr int NBINS_MAX = 1024;
static constexpr int SBUF = 4096;         // edges per bin_kernel block
static constexpr int BK_THREADS = 1024;
static constexpr int EPT = SBUF / BK_THREADS;   // 4 edges per thread
static constexpr int OVF_MAX = 65536;

__device__ int g_bin_cnt[NBINS_MAX];                  // zero on entry (invariant)
__device__ int g_bin[(size_t)NBINS_MAX * BIN_CAP];    // packed (dl<<17)|src
__device__ int g_ovf_cnt;                             // zero on entry (invariant)
__device__ int g_done;                                // zero on entry (invariant)
__device__ int2 g_ovf[OVF_MAX];                       // (dst, src) overflow edges

// block-wide exclusive scan, 1024 threads
__device__ __forceinline__ int block_exscan_1024(int v) {
    int lane = threadIdx.x & 31;
    int warp = threadIdx.x >> 5;   // 0..31
    int x = v;
#pragma unroll
    for (int o = 1; o < 32; o <<= 1) {
        int y = __shfl_up_sync(0xFFFFFFFFu, x, o);
        if (lane >= o) x += y;
    }
    __shared__ int wsum32[32];
    if (lane == 31) wsum32[warp] = x;
    __syncthreads();
    if (warp == 0) {
        int w = wsum32[lane];
#pragma unroll
        for (int o = 1; o < 32; o <<= 1) {
            int y = __shfl_up_sync(0xFFFFFFFFu, w, o);
            if (lane >= o) w += y;
        }
        wsum32[lane] = w;
    }
    __syncthreads();
    int base = (warp > 0) ? wsum32[warp - 1] : 0;
    return base + x - v;
}

// block-wide exclusive scan, 256 threads
__device__ __forceinline__ int block_exscan_256(int v) {
    int lane = threadIdx.x & 31;
    int warp = threadIdx.x >> 5;   // 0..7
    int x = v;
#pragma unroll
    for (int o = 1; o < 32; o <<= 1) {
        int y = __shfl_up_sync(0xFFFFFFFFu, x, o);
        if (lane >= o) x += y;
    }
    __shared__ int wsum8[8];
    if (lane == 31) wsum8[warp] = x;
    __syncthreads();
    if (warp == 0) {
        int w = (lane < 8) ? wsum8[lane] : 0;
#pragma unroll
        for (int o = 1; o < 8; o <<= 1) {
            int y = __shfl_up_sync(0xFFFFFFFFu, w, o);
            if (lane >= o) w += y;
        }
        if (lane < 8) wsum8[lane] = w;
    }
    __syncthreads();
    int base = (warp > 0) ? wsum8[warp - 1] : 0;
    return base + x - v;
}

// ---------- kernel 1: bin edges; entry-parallel mostly-coalesced flush ----------

__global__ void __launch_bounds__(BK_THREADS) bin_kernel(
    const int* __restrict__ edge_src,
    const int* __restrict__ edge_dst,
    int n_edges, int nbins) {
    __shared__ int s_hist[NBINS_MAX];
    __shared__ int s_off[NBINS_MAX];
    __shared__ int s_gbase[NBINS_MAX];
    __shared__ int s_cur[NBINS_MAX];
    __shared__ int s_buf[SBUF];
    __shared__ unsigned short s_bin[SBUF];

    int tid = threadIdx.x;
    int e0 = blockIdx.x * SBUF;
    int e1 = min(e0 + SBUF, n_edges);
    int ecnt = e1 - e0;

    if (tid < NBINS_MAX) s_hist[tid] = 0;
    __syncthreads();

    // load 4 edges/thread into registers (int4 when possible)
    int base = e0 + tid * EPT;
    int dd[EPT], ss[EPT];
    int m = 0;
    if (base + EPT <= e1) {
        int4 d = __ldg((const int4*)(edge_dst + base));
        int4 s = __ldg((const int4*)(edge_src + base));
        dd[0] = d.x; dd[1] = d.y; dd[2] = d.z; dd[3] = d.w;
        ss[0] = s.x; ss[1] = s.y; ss[2] = s.z; ss[3] = s.w;
        m = EPT;
    } else {
        for (int i = base; i < e1; ++i) {
            dd[m] = __ldg(edge_dst + i);
            ss[m] = __ldg(edge_src + i);
            ++m;
        }
    }

    // pass A: histogram over bins (from registers)
#pragma unroll
    for (int k = 0; k < EPT; ++k)
        if (k < m) atomicAdd(&s_hist[dd[k] / NPB], 1);
    __syncthreads();

    // local scan (1 entry/thread over 1024)
    {
        int h0 = s_hist[tid];
        int ex = block_exscan_1024(h0);
        s_off[tid] = ex;
        s_cur[tid] = ex;
    }
    __syncthreads();

    // reserve global space per bin (exact counts)
    if (tid < nbins) {
        int h = s_hist[tid];
        s_gbase[tid] = h ? atomicAdd(&g_bin_cnt[tid], h) : 0;
    }
    __syncthreads();

    // pass B: scatter packed edges + bin ids into smem staging
#pragma unroll
    for (int k = 0; k < EPT; ++k) {
        if (k < m) {
            int bin = dd[k] / NPB;
            int dl = dd[k] - bin * NPB;
            int pos = atomicAdd(&s_cur[bin], 1);
            s_buf[pos] = (dl << 17) | ss[k];
            s_bin[pos] = (unsigned short)bin;
        }
    }
    __syncthreads();

    // flush: entry-parallel; adjacent entries (same bin) target adjacent
    // global slots -> mostly-coalesced stores
    for (int i = tid; i < ecnt; i += BK_THREADS) {
        int bin = s_bin[i];
        int v = s_buf[i];
        int gpos = s_gbase[bin] + (i - s_off[bin]);
        if (gpos < BIN_CAP) {
            g_bin[(size_t)bin * BIN_CAP + gpos] = v;
        } else {
            int o = atomicAdd(&g_ovf_cnt, 1);
            if (o < OVF_MAX)
                g_ovf[o] = make_int2(bin * NPB + (v >> 17), v & 0x1FFFF);
        }
    }
}

// ---------- kernel 2: per-bin counting sort + fp32 gather + inline overflow ----------

__global__ void __launch_bounds__(256) bin_gather_kernel(
    const float4* __restrict__ feat,
    const float* __restrict__ eps,
    float4* __restrict__ out,
    int n_nodes) {
    __shared__ int s_hist[NPB + 2];
    __shared__ int s_off[NPB + 2];
    __shared__ int s_cur[NPB + 2];
    __shared__ int s_in[BIN_CAP];
    __shared__ int s_src[BIN_CAP];
    __shared__ int s_ovn;

    int tid = threadIdx.x;
    int b = blockIdx.x;
    int node0 = b * NPB;
    int nloc = min(NPB, n_nodes - node0);

    int cnt = g_bin_cnt[b];
    int used = cnt < BIN_CAP ? cnt : BIN_CAP;
    const int* bsrc = g_bin + (size_t)b * BIN_CAP;

    for (int j = tid; j < NPB + 2; j += 256) s_hist[j] = 0;
    if (tid == 0) {
        int n = g_ovf_cnt;
        s_ovn = n < OVF_MAX ? n : OVF_MAX;
    }

    // stage the bin into SMEM (coalesced, once)
    for (int i = tid; i < used; i += 256) s_in[i] = __ldg(bsrc + i);
    __syncthreads();

    // histogram over local nodes (from SMEM)
    for (int i = tid; i < used; i += 256)
        atomicAdd(&s_hist[s_in[i] >> 17], 1);
    __syncthreads();

    // scan (1 entry/thread covers 256 >= NPB+2)
    {
        int j0 = tid;
        int h0 = (j0 < NPB + 2) ? s_hist[j0] : 0;
        int ex = block_exscan_256(h0);
        if (j0 < NPB + 2) { s_off[j0] = ex; s_cur[j0] = ex; }
    }
    __syncthreads();

    // counting-scatter srcs grouped by local node (SMEM -> SMEM)
    for (int i = tid; i < used; i += 256) {
        int v = s_in[i];
        int pos = atomicAdd(&s_cur[v >> 17], 1);
        s_src[pos] = v & 0x1FFFF;
    }
    __syncthreads();

    // gather: 16 groups x 16 lanes; group g handles nodes g, g+16, ...
    int group = tid >> 4;
    int lane = tid & 15;
    float sc = 1.0f + __ldg(eps);
    int ovn = s_ovn;

    for (int nl = group; nl < nloc; nl += 16) {
        int node = node0 + nl;
        int beg = s_off[nl];
        int end = s_off[nl + 1];

        float4 acc = make_float4(0.f, 0.f, 0.f, 0.f);
        int e = beg;
        for (; e + 4 <= end; e += 4) {
            int s0 = s_src[e];
            int s1 = s_src[e + 1];
            int s2 = s_src[e + 2];
            int s3 = s_src[e + 3];
            float4 v0 = __ldg(feat + (size_t)s0 * D4 + lane);
            float4 v1 = __ldg(feat + (size_t)s1 * D4 + lane);
            float4 v2 = __ldg(feat + (size_t)s2 * D4 + lane);
            float4 v3 = __ldg(feat + (size_t)s3 * D4 + lane);
            acc.x += v0.x + v1.x + v2.x + v3.x;
            acc.y += v0.y + v1.y + v2.y + v3.y;
            acc.z += v0.z + v1.z + v2.z + v3.z;
            acc.w += v0.w + v1.w + v2.w + v3.w;
        }
        for (; e < end; ++e) {
            int s = s_src[e];
            float4 v = __ldg(feat + (size_t)s * D4 + lane);
            acc.x += v.x; acc.y += v.y; acc.z += v.z; acc.w += v.w;
        }

        // inline overflow application (expected ovn == 0)
        for (int k = 0; k < ovn; ++k) {
            int2 oe = g_ovf[k];
            if (oe.x == node) {
                float4 v = __ldg(feat + (size_t)oe.y * D4 + lane);
                acc.x += v.x; acc.y += v.y; acc.z += v.z; acc.w += v.w;
            }
        }

        float4 f = __ldg(feat + (size_t)node * D4 + lane);
        float4 o;
        o.x = fmaf(sc, f.x, acc.x);
        o.y = fmaf(sc, f.y, acc.y);
        o.z = fmaf(sc, f.z, acc.z);
        o.w = fmaf(sc, f.w, acc.w);
        out[(size_t)node * D4 + lane] = o;
    }

    // restore invariants for next call
    __syncthreads();
    if (tid == 0) {
        g_bin_cnt[b] = 0;
        int t = atomicAdd(&g_done, 1);
        if (t == (int)gridDim.x - 1) {   // last block: all others already read g_ovf_cnt
            g_done = 0;
            g_ovf_cnt = 0;
        }
    }
}

// ---------- fallback (atomic) path for unexpected shapes ----------

__global__ void gin_init_kernel(const float4* __restrict__ feat,
                                const float* __restrict__ eps,
                                float4* __restrict__ out,
                                int n4) {
    int i = blockIdx.x * blockDim.x + threadIdx.x;
    if (i >= n4) return;
    float s = 1.0f + __ldg(eps);
    float4 f = __ldg(feat + i);
    f.x *= s; f.y *= s; f.z *= s; f.w *= s;
    out[i] = f;
}

__global__ void __launch_bounds__(256) gin_edge_atomic_kernel(
    const float4* __restrict__ feat,
    const int* __restrict__ edge_src,
    const int* __restrict__ edge_dst,
    float4* __restrict__ out,
    int n_edges) {
    int gid = blockIdx.x * blockDim.x + threadIdx.x;
    int eid = gid >> 4;
    int lane = gid & 15;
    if (eid >= n_edges) return;
    int s = __ldg(edge_src + eid);
    int d = __ldg(edge_dst + eid);
    float4 v = __ldg(feat + (size_t)s * D4 + lane);
    float4* dst = out + (size_t)d * D4 + lane;
    asm volatile(
        "red.global.add.v4.f32 [%0], {%1, %2, %3, %4};"
        :: "l"(dst), "f"(v.x), "f"(v.y), "f"(v.z), "f"(v.w)
        : "memory");
}

extern "C" void kernel_launch(void* const* d_in, const int* in_sizes, int n_in,
                              void* d_out, int out_size) {
    const float* feat     = (const float*)d_in[0];
    const float* eps      = (const float*)d_in[1];
    const int*   edge_src = (const int*)d_in[2];
    const int*   edge_dst = (const int*)d_in[3];
    float*       out      = (float*)d_out;

    int n_feat  = in_sizes[0];          // N * 64
    int n_edges = in_sizes[2];          // E
    int n_nodes = n_feat / 64;

    int nbins = (n_nodes + NPB - 1) / NPB;

    // src must fit in 17 bits; bins within static scratch
    if (n_nodes > 102400 || nbins > NBINS_MAX) {
        int n4 = n_feat / 4;
        gin_init_kernel<<<(n4 + 255) / 256, 256>>>(
            (const float4*)feat, eps, (float4*)out, n4);
        long long total = (long long)n_edges * 16;
        gin_edge_atomic_kernel<<<(int)((total + 255) / 256), 256>>>(
            (const float4*)feat, edge_src, edge_dst, (float4*)out, n_edges);
        return;
    }

    // 1. bin edges (g_bin_cnt zero by invariant)
    int nblk = (n_edges + SBUF - 1) / SBUF;
    bin_kernel<<<nblk, BK_THREADS>>>(edge_src, edge_dst, n_edges, nbins);

    // 2. per-bin SMEM sort + gather + residual; applies overflow inline;
    //    re-zeroes g_bin_cnt, g_ovf_cnt, g_done
    bin_gather_kernel<<<nbins, 256>>>(
        (const float4*)feat, eps, (float4*)out, n_nodes);
}

// round 16
// speedup vs baseline: 1.1286x; 1.0209x over previous
#include <cuda_runtime.h>
#include <cstdint>

// GINConv: out = (1+eps)*feat + segment_sum(feat[edge_src] -> edge_dst)
// N=100000 nodes, D=64 fp32, E=1200000 edges.
//
// Round-16: gather is pinned at the LTS structural limit (occupancy and
// byte-reduction experiments both neutral/negative); keep NPB=100 (best
// gather, 28.4us). bin_kernel cost is per-block phase fixed cost (R7->R10:
// 586->293 blocks gave 15.3->11.8us). Halve again: SBUF 8192, grid 147
// (1 block/SM, 1024 thr, EPT=8). s_buf/s_bin move to dynamic smem (64KB
// total > 48KB static limit); attribute set host-side (not captured).

static constexpr int D4 = 16;             // 64 floats = 16 float4 per row
static constexpr int NPB = 100;           // nodes per bin -> 1000 bins for N=100000
static constexpr int BIN_CAP = 1472;      // mean 1200 + ~7.9 sigma
static constexpr int NBINS_MAX = 1024;
static constexpr int SBUF = 8192;         // edges per bin_kernel block
static constexpr int BK_THREADS = 1024;
static constexpr int EPT = SBUF / BK_THREADS;   // 8 edges per thread
static constexpr int OVF_MAX = 65536;
static constexpr int BK_DYN_SMEM = SBUF * 4 + SBUF * 2;  // s_buf + s_bin = 49152

__device__ int g_bin_cnt[NBINS_MAX];                  // zero on entry (invariant)
__device__ int g_bin[(size_t)NBINS_MAX * BIN_CAP];    // packed (dl<<17)|src
__device__ int g_ovf_cnt;                             // zero on entry (invariant)
__device__ int g_done;                                // zero on entry (invariant)
__device__ int2 g_ovf[OVF_MAX];                       // (dst, src) overflow edges

// block-wide exclusive scan, 1024 threads
__device__ __forceinline__ int block_exscan_1024(int v) {
    int lane = threadIdx.x & 31;
    int warp = threadIdx.x >> 5;   // 0..31
    int x = v;
#pragma unroll
    for (int o = 1; o < 32; o <<= 1) {
        int y = __shfl_up_sync(0xFFFFFFFFu, x, o);
        if (lane >= o) x += y;
    }
    __shared__ int wsum32[32];
    if (lane == 31) wsum32[warp] = x;
    __syncthreads();
    if (warp == 0) {
        int w = wsum32[lane];
#pragma unroll
        for (int o = 1; o < 32; o <<= 1) {
            int y = __shfl_up_sync(0xFFFFFFFFu, w, o);
            if (lane >= o) w += y;
        }
        wsum32[lane] = w;
    }
    __syncthreads();
    int base = (warp > 0) ? wsum32[warp - 1] : 0;
    return base + x - v;
}

// block-wide exclusive scan, 256 threads
__device__ __forceinline__ int block_exscan_256(int v) {
    int lane = threadIdx.x & 31;
    int warp = threadIdx.x >> 5;   // 0..7
    int x = v;
#pragma unroll
    for (int o = 1; o < 32; o <<= 1) {
        int y = __shfl_up_sync(0xFFFFFFFFu, x, o);
        if (lane >= o) x += y;
    }
    __shared__ int wsum8[8];
    if (lane == 31) wsum8[warp] = x;
    __syncthreads();
    if (warp == 0) {
        int w = (lane < 8) ? wsum8[lane] : 0;
#pragma unroll
        for (int o = 1; o < 8; o <<= 1) {
            int y = __shfl_up_sync(0xFFFFFFFFu, w, o);
            if (lane >= o) w += y;
        }
        if (lane < 8) wsum8[lane] = w;
    }
    __syncthreads();
    int base = (warp > 0) ? wsum8[warp - 1] : 0;
    return base + x - v;
}

// ---------- kernel 1: bin edges; entry-parallel mostly-coalesced flush ----------

__global__ void __launch_bounds__(BK_THREADS) bin_kernel(
    const int* __restrict__ edge_src,
    const int* __restrict__ edge_dst,
    int n_edges, int nbins) {
    __shared__ int s_hist[NBINS_MAX];
    __shared__ int s_off[NBINS_MAX];
    __shared__ int s_gbase[NBINS_MAX];
    __shared__ int s_cur[NBINS_MAX];
    extern __shared__ int dyn_smem[];
    int* s_buf = dyn_smem;                                      // SBUF ints
    unsigned short* s_bin = (unsigned short*)(dyn_smem + SBUF); // SBUF ushorts

    int tid = threadIdx.x;
    int e0 = blockIdx.x * SBUF;
    int e1 = min(e0 + SBUF, n_edges);
    int ecnt = e1 - e0;

    if (tid < NBINS_MAX) s_hist[tid] = 0;
    __syncthreads();

    // load 8 edges/thread into registers (2x int4 when possible)
    int base = e0 + tid * EPT;
    int dd[EPT], ss[EPT];
    int m = 0;
    if (base + EPT <= e1) {
        int4 d0 = __ldg((const int4*)(edge_dst + base));
        int4 d1 = __ldg((const int4*)(edge_dst + base + 4));
        int4 s0 = __ldg((const int4*)(edge_src + base));
        int4 s1 = __ldg((const int4*)(edge_src + base + 4));
        dd[0] = d0.x; dd[1] = d0.y; dd[2] = d0.z; dd[3] = d0.w;
        dd[4] = d1.x; dd[5] = d1.y; dd[6] = d1.z; dd[7] = d1.w;
        ss[0] = s0.x; ss[1] = s0.y; ss[2] = s0.z; ss[3] = s0.w;
        ss[4] = s1.x; ss[5] = s1.y; ss[6] = s1.z; ss[7] = s1.w;
        m = EPT;
    } else {
        for (int i = base; i < e1; ++i) {
            dd[m] = __ldg(edge_dst + i);
            ss[m] = __ldg(edge_src + i);
            ++m;
        }
    }

    // pass A: histogram over bins (from registers)
#pragma unroll
    for (int k = 0; k < EPT; ++k)
        if (k < m) atomicAdd(&s_hist[dd[k] / NPB], 1);
    __syncthreads();

    // local scan (1 entry/thread over 1024)
    {
        int h0 = s_hist[tid];
        int ex = block_exscan_1024(h0);
        s_off[tid] = ex;
        s_cur[tid] = ex;
    }
    __syncthreads();

    // reserve global space per bin (exact counts)
    if (tid < nbins) {
        int h = s_hist[tid];
        s_gbase[tid] = h ? atomicAdd(&g_bin_cnt[tid], h) : 0;
    }
    __syncthreads();

    // pass B: scatter packed edges + bin ids into smem staging
#pragma unroll
    for (int k = 0; k < EPT; ++k) {
        if (k < m) {
            int bin = dd[k] / NPB;
            int dl = dd[k] - bin * NPB;
            int pos = atomicAdd(&s_cur[bin], 1);
            s_buf[pos] = (dl << 17) | ss[k];
            s_bin[pos] = (unsigned short)bin;
        }
    }
    __syncthreads();

    // flush: entry-parallel; adjacent entries (same bin) target adjacent
    // global slots -> mostly-coalesced stores
    for (int i = tid; i < ecnt; i += BK_THREADS) {
        int bin = s_bin[i];
        int v = s_buf[i];
        int gpos = s_gbase[bin] + (i - s_off[bin]);
        if (gpos < BIN_CAP) {
            g_bin[(size_t)bin * BIN_CAP + gpos] = v;
        } else {
            int o = atomicAdd(&g_ovf_cnt, 1);
            if (o < OVF_MAX)
                g_ovf[o] = make_int2(bin * NPB + (v >> 17), v & 0x1FFFF);
        }
    }
}

// ---------- kernel 2: per-bin counting sort + fp32 gather + inline overflow ----------

__global__ void __launch_bounds__(256) bin_gather_kernel(
    const float4* __restrict__ feat,
    const float* __restrict__ eps,
    float4* __restrict__ out,
    int n_nodes) {
    __shared__ int s_hist[NPB + 2];
    __shared__ int s_off[NPB + 2];
    __shared__ int s_cur[NPB + 2];
    __shared__ int s_in[BIN_CAP];
    __shared__ int s_src[BIN_CAP];
    __shared__ int s_ovn;

    int tid = threadIdx.x;
    int b = blockIdx.x;
    int node0 = b * NPB;
    int nloc = min(NPB, n_nodes - node0);

    int cnt = g_bin_cnt[b];
    int used = cnt < BIN_CAP ? cnt : BIN_CAP;
    const int* bsrc = g_bin + (size_t)b * BIN_CAP;

    for (int j = tid; j < NPB + 2; j += 256) s_hist[j] = 0;
    if (tid == 0) {
        int n = g_ovf_cnt;
        s_ovn = n < OVF_MAX ? n : OVF_MAX;
    }

    // stage the bin into SMEM (coalesced, once)
    for (int i = tid; i < used; i += 256) s_in[i] = __ldg(bsrc + i);
    __syncthreads();

    // histogram over local nodes (from SMEM)
    for (int i = tid; i < used; i += 256)
        atomicAdd(&s_hist[s_in[i] >> 17], 1);
    __syncthreads();

    // scan (1 entry/thread covers 256 >= NPB+2)
    {
        int j0 = tid;
        int h0 = (j0 < NPB + 2) ? s_hist[j0] : 0;
        int ex = block_exscan_256(h0);
        if (j0 < NPB + 2) { s_off[j0] = ex; s_cur[j0] = ex; }
    }
    __syncthreads();

    // counting-scatter srcs grouped by local node (SMEM -> SMEM)
    for (int i = tid; i < used; i += 256) {
        int v = s_in[i];
        int pos = atomicAdd(&s_cur[v >> 17], 1);
        s_src[pos] = v & 0x1FFFF;
    }
    __syncthreads();

    // gather: 16 groups x 16 lanes; group g handles nodes g, g+16, ...
    int group = tid >> 4;
    int lane = tid & 15;
    float sc = 1.0f + __ldg(eps);
    int ovn = s_ovn;

    for (int nl = group; nl < nloc; nl += 16) {
        int node = node0 + nl;
        int beg = s_off[nl];
        int end = s_off[nl + 1];

        float4 acc = make_float4(0.f, 0.f, 0.f, 0.f);
        int e = beg;
        for (; e + 4 <= end; e += 4) {
            int s0 = s_src[e];
            int s1 = s_src[e + 1];
            int s2 = s_src[e + 2];
            int s3 = s_src[e + 3];
            float4 v0 = __ldg(feat + (size_t)s0 * D4 + lane);
            float4 v1 = __ldg(feat + (size_t)s1 * D4 + lane);
            float4 v2 = __ldg(feat + (size_t)s2 * D4 + lane);
            float4 v3 = __ldg(feat + (size_t)s3 * D4 + lane);
            acc.x += v0.x + v1.x + v2.x + v3.x;
            acc.y += v0.y + v1.y + v2.y + v3.y;
            acc.z += v0.z + v1.z + v2.z + v3.z;
            acc.w += v0.w + v1.w + v2.w + v3.w;
        }
        for (; e < end; ++e) {
            int s = s_src[e];
            float4 v = __ldg(feat + (size_t)s * D4 + lane);
            acc.x += v.x; acc.y += v.y; acc.z += v.z; acc.w += v.w;
        }

        // inline overflow application (expected ovn == 0)
        for (int k = 0; k < ovn; ++k) {
            int2 oe = g_ovf[k];
            if (oe.x == node) {
                float4 v = __ldg(feat + (size_t)oe.y * D4 + lane);
                acc.x += v.x; acc.y += v.y; acc.z += v.z; acc.w += v.w;
            }
        }

        float4 f = __ldg(feat + (size_t)node * D4 + lane);
        float4 o;
        o.x = fmaf(sc, f.x, acc.x);
        o.y = fmaf(sc, f.y, acc.y);
        o.z = fmaf(sc, f.z, acc.z);
        o.w = fmaf(sc, f.w, acc.w);
        out[(size_t)node * D4 + lane] = o;
    }

    // restore invariants for next call
    __syncthreads();
    if (tid == 0) {
        g_bin_cnt[b] = 0;
        int t = atomicAdd(&g_done, 1);
        if (t == (int)gridDim.x - 1) {   // last block: all others already read g_ovf_cnt
            g_done = 0;
            g_ovf_cnt = 0;
        }
    }
}

// ---------- fallback (atomic) path for unexpected shapes ----------

__global__ void gin_init_kernel(const float4* __restrict__ feat,
                                const float* __restrict__ eps,
                                float4* __restrict__ out,
                                int n4) {
    int i = blockIdx.x * blockDim.x + threadIdx.x;
    if (i >= n4) return;
    float s = 1.0f + __ldg(eps);
    float4 f = __ldg(feat + i);
    f.x *= s; f.y *= s; f.z *= s; f.w *= s;
    out[i] = f;
}

__global__ void __launch_bounds__(256) gin_edge_atomic_kernel(
    const float4* __restrict__ feat,
    const int* __restrict__ edge_src,
    const int* __restrict__ edge_dst,
    float4* __restrict__ out,
    int n_edges) {
    int gid = blockIdx.x * blockDim.x + threadIdx.x;
    int eid = gid >> 4;
    int lane = gid & 15;
    if (eid >= n_edges) return;
    int s = __ldg(edge_src + eid);
    int d = __ldg(edge_dst + eid);
    float4 v = __ldg(feat + (size_t)s * D4 + lane);
    float4* dst = out + (size_t)d * D4 + lane;
    asm volatile(
        "red.global.add.v4.f32 [%0], {%1, %2, %3, %4};"
        :: "l"(dst), "f"(v.x), "f"(v.y), "f"(v.z), "f"(v.w)
        : "memory");
}

extern "C" void kernel_launch(void* const* d_in, const int* in_sizes, int n_in,
                              void* d_out, int out_size) {
    const float* feat     = (const float*)d_in[0];
    const float* eps      = (const float*)d_in[1];
    const int*   edge_src = (const int*)d_in[2];
    const int*   edge_dst = (const int*)d_in[3];
    float*       out      = (float*)d_out;

    int n_feat  = in_sizes[0];          // N * 64
    int n_edges = in_sizes[2];          // E
    int n_nodes = n_feat / 64;

    int nbins = (n_nodes + NPB - 1) / NPB;

    // src must fit in 17 bits; bins within static scratch
    if (n_nodes > 102400 || nbins > NBINS_MAX) {
        int n4 = n_feat / 4;
        gin_init_kernel<<<(n4 + 255) / 256, 256>>>(
            (const float4*)feat, eps, (float4*)out, n4);
        long long total = (long long)n_edges * 16;
        gin_edge_atomic_kernel<<<(int)((total + 255) / 256), 256>>>(
            (const float4*)feat, edge_src, edge_dst, (float4*)out, n_edges);
        return;
    }

    // allow >48KB dynamic smem for bin_kernel (idempotent host-side call;
    // not a stream op, not captured, no allocation)
    static bool attr_set = false;
    if (!attr_set) {
        cudaFuncSetAttribute(bin_kernel,
                             cudaFuncAttributeMaxDynamicSharedMemorySize,
                             BK_DYN_SMEM);
        attr_set = true;
    }

    // 1. bin edges (g_bin_cnt zero by invariant)
    int nblk = (n_edges + SBUF - 1) / SBUF;
    bin_kernel<<<nblk, BK_THREADS, BK_DYN_SMEM>>>(edge_src, edge_dst,
                                                  n_edges, nbins);

    // 2. per-bin SMEM sort + gather + residual; applies overflow inline;
    //    re-zeroes g_bin_cnt, g_ovf_cnt, g_done
    bin_gather_kernel<<<nbins, 256>>>(
        (const float4*)feat, eps, (float4*)out, n_nodes);
}

// round 17
// speedup vs baseline: 1.1682x; 1.0351x over previous
#include <cuda_runtime.h>
#include <cstdint>

// GINConv: out = (1+eps)*feat + segment_sum(feat[edge_src] -> edge_dst)
// N=100000 nodes, D=64 fp32, E=1200000 edges.
//
// Round-17: gather re-shaped for perfect residency: 592 blocks (= 4 x 148
// SMs exactly) x 512 threads = 2048 thr/SM (100% occ, zero wave imbalance;
// R16 had 79% with 6.76 blocks/SM). NPB 169, BIN_CAP 2368 (mean+7.5sigma).
// Stage+histogram fused into one pass (one fewer barrier + smem sweep per
// block). bin_kernel identical to R16 (147 blocks, 1024 thr, dyn smem).

static constexpr int D4 = 16;             // 64 floats = 16 float4 per row
static constexpr int NPB = 169;           // nodes per bin -> 592 bins for N=100000
static constexpr int BIN_CAP = 2368;      // mean 2028 + ~7.5 sigma
static constexpr int NBINS_MAX = 1024;
static constexpr int SBUF = 8192;         // edges per bin_kernel block
static constexpr int BK_THREADS = 1024;
static constexpr int EPT = SBUF / BK_THREADS;   // 8 edges per thread
static constexpr int GT_THREADS = 512;    // gather threads per block
static constexpr int OVF_MAX = 65536;
static constexpr int BK_DYN_SMEM = SBUF * 4 + SBUF * 2;  // s_buf + s_bin = 49152

__device__ int g_bin_cnt[NBINS_MAX];                  // zero on entry (invariant)
__device__ int g_bin[(size_t)NBINS_MAX * BIN_CAP];    // packed (dl<<17)|src
__device__ int g_ovf_cnt;                             // zero on entry (invariant)
__device__ int g_done;                                // zero on entry (invariant)
__device__ int2 g_ovf[OVF_MAX];                       // (dst, src) overflow edges

// block-wide exclusive scan, 1024 threads
__device__ __forceinline__ int block_exscan_1024(int v) {
    int lane = threadIdx.x & 31;
    int warp = threadIdx.x >> 5;   // 0..31
    int x = v;
#pragma unroll
    for (int o = 1; o < 32; o <<= 1) {
        int y = __shfl_up_sync(0xFFFFFFFFu, x, o);
        if (lane >= o) x += y;
    }
    __shared__ int wsum32[32];
    if (lane == 31) wsum32[warp] = x;
    __syncthreads();
    if (warp == 0) {
        int w = wsum32[lane];
#pragma unroll
        for (int o = 1; o < 32; o <<= 1) {
            int y = __shfl_up_sync(0xFFFFFFFFu, w, o);
            if (lane >= o) w += y;
        }
        wsum32[lane] = w;
    }
    __syncthreads();
    int base = (warp > 0) ? wsum32[warp - 1] : 0;
    return base + x - v;
}

// block-wide exclusive scan, 512 threads
__device__ __forceinline__ int block_exscan_512(int v) {
    int lane = threadIdx.x & 31;
    int warp = threadIdx.x >> 5;   // 0..15
    int x = v;
#pragma unroll
    for (int o = 1; o < 32; o <<= 1) {
        int y = __shfl_up_sync(0xFFFFFFFFu, x, o);
        if (lane >= o) x += y;
    }
    __shared__ int wsum16[16];
    if (lane == 31) wsum16[warp] = x;
    __syncthreads();
    if (warp == 0) {
        int w = (lane < 16) ? wsum16[lane] : 0;
#pragma unroll
        for (int o = 1; o < 16; o <<= 1) {
            int y = __shfl_up_sync(0xFFFFFFFFu, w, o);
            if (lane >= o) w += y;
        }
        if (lane < 16) wsum16[lane] = w;
    }
    __syncthreads();
    int base = (warp > 0) ? wsum16[warp - 1] : 0;
    return base + x - v;
}

// ---------- kernel 1: bin edges; entry-parallel mostly-coalesced flush ----------

__global__ void __launch_bounds__(BK_THREADS) bin_kernel(
    const int* __restrict__ edge_src,
    const int* __restrict__ edge_dst,
    int n_edges, int nbins) {
    __shared__ int s_hist[NBINS_MAX];
    __shared__ int s_off[NBINS_MAX];
    __shared__ int s_gbase[NBINS_MAX];
    __shared__ int s_cur[NBINS_MAX];
    extern __shared__ int dyn_smem[];
    int* s_buf = dyn_smem;                                      // SBUF ints
    unsigned short* s_bin = (unsigned short*)(dyn_smem + SBUF); // SBUF ushorts

    int tid = threadIdx.x;
    int e0 = blockIdx.x * SBUF;
    int e1 = min(e0 + SBUF, n_edges);
    int ecnt = e1 - e0;

    if (tid < NBINS_MAX) s_hist[tid] = 0;
    __syncthreads();

    // load 8 edges/thread into registers (2x int4 when possible)
    int base = e0 + tid * EPT;
    int dd[EPT], ss[EPT];
    int m = 0;
    if (base + EPT <= e1) {
        int4 d0 = __ldg((const int4*)(edge_dst + base));
        int4 d1 = __ldg((const int4*)(edge_dst + base + 4));
        int4 s0 = __ldg((const int4*)(edge_src + base));
        int4 s1 = __ldg((const int4*)(edge_src + base + 4));
        dd[0] = d0.x; dd[1] = d0.y; dd[2] = d0.z; dd[3] = d0.w;
        dd[4] = d1.x; dd[5] = d1.y; dd[6] = d1.z; dd[7] = d1.w;
        ss[0] = s0.x; ss[1] = s0.y; ss[2] = s0.z; ss[3] = s0.w;
        ss[4] = s1.x; ss[5] = s1.y; ss[6] = s1.z; ss[7] = s1.w;
        m = EPT;
    } else {
        for (int i = base; i < e1; ++i) {
            dd[m] = __ldg(edge_dst + i);
            ss[m] = __ldg(edge_src + i);
            ++m;
        }
    }

    // pass A: histogram over bins (from registers)
#pragma unroll
    for (int k = 0; k < EPT; ++k)
        if (k < m) atomicAdd(&s_hist[dd[k] / NPB], 1);
    __syncthreads();

    // local scan (1 entry/thread over 1024)
    {
        int h0 = s_hist[tid];
        int ex = block_exscan_1024(h0);
        s_off[tid] = ex;
        s_cur[tid] = ex;
    }
    __syncthreads();

    // reserve global space per bin (exact counts)
    if (tid < nbins) {
        int h = s_hist[tid];
        s_gbase[tid] = h ? atomicAdd(&g_bin_cnt[tid], h) : 0;
    }
    __syncthreads();

    // pass B: scatter packed edges + bin ids into smem staging
#pragma unroll
    for (int k = 0; k < EPT; ++k) {
        if (k < m) {
            int bin = dd[k] / NPB;
            int dl = dd[k] - bin * NPB;
            int pos = atomicAdd(&s_cur[bin], 1);
            s_buf[pos] = (dl << 17) | ss[k];
            s_bin[pos] = (unsigned short)bin;
        }
    }
    __syncthreads();

    // flush: entry-parallel; adjacent entries (same bin) target adjacent
    // global slots -> mostly-coalesced stores
    for (int i = tid; i < ecnt; i += BK_THREADS) {
        int bin = s_bin[i];
        int v = s_buf[i];
        int gpos = s_gbase[bin] + (i - s_off[bin]);
        if (gpos < BIN_CAP) {
            g_bin[(size_t)bin * BIN_CAP + gpos] = v;
        } else {
            int o = atomicAdd(&g_ovf_cnt, 1);
            if (o < OVF_MAX)
                g_ovf[o] = make_int2(bin * NPB + (v >> 17), v & 0x1FFFF);
        }
    }
}

// ---------- kernel 2: per-bin counting sort + fp32 gather + inline overflow ----------

__global__ void __launch_bounds__(GT_THREADS) bin_gather_kernel(
    const float4* __restrict__ feat,
    const float* __restrict__ eps,
    float4* __restrict__ out,
    int n_nodes) {
    __shared__ int s_hist[NPB + 2];
    __shared__ int s_off[NPB + 2];
    __shared__ int s_cur[NPB + 2];
    __shared__ int s_in[BIN_CAP];
    __shared__ int s_src[BIN_CAP];
    __shared__ int s_ovn;

    int tid = threadIdx.x;
    int b = blockIdx.x;
    int node0 = b * NPB;
    int nloc = min(NPB, n_nodes - node0);

    int cnt = g_bin_cnt[b];
    int used = cnt < BIN_CAP ? cnt : BIN_CAP;
    const int* bsrc = g_bin + (size_t)b * BIN_CAP;

    for (int j = tid; j < NPB + 2; j += GT_THREADS) s_hist[j] = 0;
    if (tid == 0) {
        int n = g_ovf_cnt;
        s_ovn = n < OVF_MAX ? n : OVF_MAX;
    }
    __syncthreads();

    // fused: stage the bin into SMEM AND histogram from the loaded register
    for (int i = tid; i < used; i += GT_THREADS) {
        int v = __ldg(bsrc + i);
        s_in[i] = v;
        atomicAdd(&s_hist[v >> 17], 1);
    }
    __syncthreads();

    // scan (1 entry/thread covers 512 >= NPB+2)
    {
        int j0 = tid;
        int h0 = (j0 < NPB + 2) ? s_hist[j0] : 0;
        int ex = block_exscan_512(h0);
        if (j0 < NPB + 2) { s_off[j0] = ex; s_cur[j0] = ex; }
    }
    __syncthreads();

    // counting-scatter srcs grouped by local node (SMEM -> SMEM)
    for (int i = tid; i < used; i += GT_THREADS) {
        int v = s_in[i];
        int pos = atomicAdd(&s_cur[v >> 17], 1);
        s_src[pos] = v & 0x1FFFF;
    }
    __syncthreads();

    // gather: 32 groups x 16 lanes; group g handles nodes g, g+32, ...
    int group = tid >> 4;          // 0..31
    int lane = tid & 15;
    float sc = 1.0f + __ldg(eps);
    int ovn = s_ovn;

    for (int nl = group; nl < nloc; nl += GT_THREADS / 16) {
        int node = node0 + nl;
        int beg = s_off[nl];
        int end = s_off[nl + 1];

        float4 acc = make_float4(0.f, 0.f, 0.f, 0.f);
        int e = beg;
        for (; e + 4 <= end; e += 4) {
            int s0 = s_src[e];
            int s1 = s_src[e + 1];
            int s2 = s_src[e + 2];
            int s3 = s_src[e + 3];
            float4 v0 = __ldg(feat + (size_t)s0 * D4 + lane);
            float4 v1 = __ldg(feat + (size_t)s1 * D4 + lane);
            float4 v2 = __ldg(feat + (size_t)s2 * D4 + lane);
            float4 v3 = __ldg(feat + (size_t)s3 * D4 + lane);
            acc.x += v0.x + v1.x + v2.x + v3.x;
            acc.y += v0.y + v1.y + v2.y + v3.y;
            acc.z += v0.z + v1.z + v2.z + v3.z;
            acc.w += v0.w + v1.w + v2.w + v3.w;
        }
        for (; e < end; ++e) {
            int s = s_src[e];
            float4 v = __ldg(feat + (size_t)s * D4 + lane);
            acc.x += v.x; acc.y += v.y; acc.z += v.z; acc.w += v.w;
        }

        // inline overflow application (expected ovn == 0)
        for (int k = 0; k < ovn; ++k) {
            int2 oe = g_ovf[k];
            if (oe.x == node) {
                float4 v = __ldg(feat + (size_t)oe.y * D4 + lane);
                acc.x += v.x; acc.y += v.y; acc.z += v.z; acc.w += v.w;
            }
        }

        float4 f = __ldg(feat + (size_t)node * D4 + lane);
        float4 o;
        o.x = fmaf(sc, f.x, acc.x);
        o.y = fmaf(sc, f.y, acc.y);
        o.z = fmaf(sc, f.z, acc.z);
        o.w = fmaf(sc, f.w, acc.w);
        out[(size_t)node * D4 + lane] = o;
    }

    // restore invariants for next call
    __syncthreads();
    if (tid == 0) {
        g_bin_cnt[b] = 0;
        int t = atomicAdd(&g_done, 1);
        if (t == (int)gridDim.x - 1) {   // last block: all others already read g_ovf_cnt
            g_done = 0;
            g_ovf_cnt = 0;
        }
    }
}

// ---------- fallback (atomic) path for unexpected shapes ----------

__global__ void gin_init_kernel(const float4* __restrict__ feat,
                                const float* __restrict__ eps,
                                float4* __restrict__ out,
                                int n4) {
    int i = blockIdx.x * blockDim.x + threadIdx.x;
    if (i >= n4) return;
    float s = 1.0f + __ldg(eps);
    float4 f = __ldg(feat + i);
    f.x *= s; f.y *= s; f.z *= s; f.w *= s;
    out[i] = f;
}

__global__ void __launch_bounds__(256) gin_edge_atomic_kernel(
    const float4* __restrict__ feat,
    const int* __restrict__ edge_src,
    const int* __restrict__ edge_dst,
    float4* __restrict__ out,
    int n_edges) {
    int gid = blockIdx.x * blockDim.x + threadIdx.x;
    int eid = gid >> 4;
    int lane = gid & 15;
    if (eid >= n_edges) return;
    int s = __ldg(edge_src + eid);
    int d = __ldg(edge_dst + eid);
    float4 v = __ldg(feat + (size_t)s * D4 + lane);
    float4* dst = out + (size_t)d * D4 + lane;
    asm volatile(
        "red.global.add.v4.f32 [%0], {%1, %2, %3, %4};"
        :: "l"(dst), "f"(v.x), "f"(v.y), "f"(v.z), "f"(v.w)
        : "memory");
}

extern "C" void kernel_launch(void* const* d_in, const int* in_sizes, int n_in,
                              void* d_out, int out_size) {
    const float* feat     = (const float*)d_in[0];
    const float* eps      = (const float*)d_in[1];
    const int*   edge_src = (const int*)d_in[2];
    const int*   edge_dst = (const int*)d_in[3];
    float*       out      = (float*)d_out;

    int n_feat  = in_sizes[0];          // N * 64
    int n_edges = in_sizes[2];          // E
    int n_nodes = n_feat / 64;

    int nbins = (n_nodes + NPB - 1) / NPB;

    // src must fit in 17 bits; bins within static scratch
    if (n_nodes > 131072 || nbins > NBINS_MAX) {
        int n4 = n_feat / 4;
        gin_init_kernel<<<(n4 + 255) / 256, 256>>>(
            (const float4*)feat, eps, (float4*)out, n4);
        long long total = (long long)n_edges * 16;
        gin_edge_atomic_kernel<<<(int)((total + 255) / 256), 256>>>(
            (const float4*)feat, edge_src, edge_dst, (float4*)out, n_edges);
        return;
    }

    // allow >48KB dynamic smem for bin_kernel (idempotent host-side call;
    // not a stream op, not captured, no allocation)
    static bool attr_set = false;
    if (!attr_set) {
        cudaFuncSetAttribute(bin_kernel,
                             cudaFuncAttributeMaxDynamicSharedMemorySize,
                             BK_DYN_SMEM);
        attr_set = true;
    }

    // 1. bin edges (g_bin_cnt zero by invariant)
    int nblk = (n_edges + SBUF - 1) / SBUF;
    bin_kernel<<<nblk, BK_THREADS, BK_DYN_SMEM>>>(edge_src, edge_dst,
                                                  n_edges, nbins);

    // 2. per-bin SMEM sort + gather + residual; applies overflow inline;
    //    re-zeroes g_bin_cnt, g_ovf_cnt, g_done
    bin_gather_kernel<<<nbins, GT_THREADS>>>(
        (const float4*)feat, eps, (float4*)out, n_nodes);
}